// round 5
// baseline (speedup 1.0000x reference)
#include <cuda_runtime.h>

// Problem constants (fixed by the reference)
#define BB 1024
#define NN 16
#define TT 256
#define NTRI (NN * (NN + 1) / 2)   // 136
#define TPB 64                     // 64 threads = 64 t-values per tile
#define NTILES (BB * (TT / TPB))   // 4096 tiles
#define GRID 760                   // 152 SMs x 5 CTAs, persistent

// Scratch for deterministic single-launch reduction (no cudaMalloc allowed)
__device__ float g_partials[GRID];
__device__ unsigned int g_count = 0;   // self-resetting arrival counter

// 16B cp.async, L1-bypass (.cg): stages global->shared with no register cost.
__device__ __forceinline__ void cp_async16(void* smem, const void* gmem) {
    unsigned s = (unsigned)__cvta_generic_to_shared(smem);
    asm volatile("cp.async.cg.shared.global [%0], [%1], 16;" :: "r"(s), "l"(gmem));
}

__global__ __launch_bounds__(TPB, 5) void gll_pipe_kernel(
    const float* __restrict__ pred,
    const float* __restrict__ targ,
    const float* __restrict__ cov,
    float* __restrict__ out)
{
    // Staging buffer: 136 cov planes + 16 pred rows + 16 targ rows,
    // 64 floats (256B) each = 43008 B. Row stride 256B -> LDS column reads
    // are perfectly bank-conflict-free.
    __shared__ __align__(16) float s_cov[NTRI][TPB];
    __shared__ __align__(16) float s_p[NN][TPB];
    __shared__ __align__(16) float s_q[NN][TPB];

    const int tid  = threadIdx.x;
    const int g16  = tid >> 4;             // 16-thread group id (0..3)
    const int l16  = tid & 15;             // lane within group
    const int lane = tid & 31;
    const int wid  = tid >> 5;

    // Issue all cp.asyncs for one tile. Compile-time-unrolled; each thread
    // issues ~42 copies, warp-contiguous 16B chunks within each 256B row.
    auto issue_tile = [&](int tile) {
        const int b  = tile >> 2;
        const int t0 = (tile & 3) << 6;
        const float* covb = cov + ((size_t)b * NN * NN) * TT + t0;
        int p = 0;
#pragma unroll
        for (int i = 0; i < NN; ++i) {
#pragma unroll
            for (int j = 0; j <= i; ++j, ++p) {
                if (g16 == (p & 3))
                    cp_async16(&s_cov[p][l16 * 4],
                               covb + (i * NN + j) * TT + l16 * 4);
            }
        }
#pragma unroll
        for (int i = 0; i < NN; ++i) {
            if (g16 == (i & 3)) {
                const size_t roff = (size_t)(b * NN + i) * TT + t0;
                cp_async16(&s_p[i][l16 * 4], pred + roff + l16 * 4);
                cp_async16(&s_q[i][l16 * 4], targ + roff + l16 * 4);
            }
        }
        asm volatile("cp.async.commit_group;");
    };

    float vsum = 0.0f;   // per-thread accumulation across tiles

    int tile = blockIdx.x;
    if (tile < NTILES) issue_tile(tile);   // prologue prefetch

    while (tile < NTILES) {
        asm volatile("cp.async.wait_group 0;" ::: "memory");
        __syncthreads();

        // smem -> registers (conflict-free column reads)
        float A[NTRI];
        float y[NN];
#pragma unroll
        for (int p = 0; p < NTRI; ++p) A[p] = s_cov[p][tid];
#pragma unroll
        for (int i = 0; i < NN; ++i)   y[i] = s_p[i][tid] - s_q[i][tid];

        __syncthreads();   // everyone done reading smem

        // Prefetch next tile NOW -> DRAM stays busy during the factorization
        const int next = tile + GRID;
        if (next < NTILES) issue_tile(next);

        // Right-looking Cholesky, forward solve fused as augmented column.
        // Pivots >= 1 (Sigma = AA^T + I): rsqrt/log safe; pivot product fits
        // fp32, so one __logf replaces 16.
        float pivprod = 1.0f;
        float quad    = 0.0f;
#pragma unroll
        for (int j = 0; j < NN; ++j) {
            const float s    = A[j * (j + 1) / 2 + j];
            pivprod *= s;
            const float invd = rsqrtf(s);

            y[j] *= invd;
            quad = fmaf(y[j], y[j], quad);
#pragma unroll
            for (int i = j + 1; i < NN; ++i) {
                A[i * (i + 1) / 2 + j] *= invd;      // L[i][j]
            }
#pragma unroll
            for (int i = j + 1; i < NN; ++i) {
                const float lij = A[i * (i + 1) / 2 + j];
                y[i] = fmaf(-lij, y[j], y[i]);
#pragma unroll
                for (int k = j + 1; k <= i; ++k) {
                    A[i * (i + 1) / 2 + k] =
                        fmaf(-lij, A[k * (k + 1) / 2 + j], A[i * (i + 1) / 2 + k]);
                }
            }
        }
        vsum += quad + __logf(pivprod);

        tile = next;
    }

    // ---- In-block reduction: warp shuffles + 2-warp smem combine
#pragma unroll
    for (int o = 16; o > 0; o >>= 1) vsum += __shfl_down_sync(0xffffffffu, vsum, o);

    __shared__ float warpsum[TPB / 32];
    __shared__ bool  isLast;
    if (lane == 0) warpsum[wid] = vsum;
    __syncthreads();

    if (tid == 0) {
        float s = warpsum[0] + warpsum[1];
        g_partials[blockIdx.x] = s;
        __threadfence();
        unsigned int c = atomicAdd(&g_count, 1u);
        isLast = (c == (unsigned int)(GRID - 1));
    }
    __syncthreads();

    // Last arriving block performs the deterministic final sum (fixed order).
    if (isLast) {
        float s = 0.0f;
#pragma unroll 4
        for (int i = tid; i < GRID; i += TPB) s += g_partials[i];
#pragma unroll
        for (int o = 16; o > 0; o >>= 1) s += __shfl_down_sync(0xffffffffu, s, o);
        if (lane == 0) warpsum[wid] = s;
        __syncthreads();
        if (tid == 0) {
            out[0] = (warpsum[0] + warpsum[1]) * (1.0f / (float)(BB * TT));
            g_count = 0;   // reset for the next graph replay
        }
    }
}

extern "C" void kernel_launch(void* const* d_in, const int* in_sizes, int n_in,
                              void* d_out, int out_size)
{
    const float* pred = (const float*)d_in[0];   // prediction [B,N,T]
    const float* targ = (const float*)d_in[1];   // target     [B,N,T]
    const float* cov  = (const float*)d_in[2];   // cov        [B,N,N,T]
    float* out = (float*)d_out;

    gll_pipe_kernel<<<GRID, TPB>>>(pred, targ, cov, out);
}

// round 7
// speedup vs baseline: 2.2791x; 2.2791x over previous
#include <cuda_runtime.h>

// Problem constants (fixed by the reference)
#define BB 1024
#define NN 16
#define TT 256
#define TPB 64                      // 64 threads = 64 (b,t) pairs, 1 thread each
#define GRID (BB * (TT / TPB))      // 4096 blocks, 4 per batch b

#define TRI(i, j) ((i) * ((i) + 1) / 2 + (j))   // packed lower-triangle index

// Scratch for deterministic single-launch reduction (no cudaMalloc allowed)
__device__ float g_partials[GRID];
__device__ unsigned int g_count = 0;   // self-resetting arrival counter

__global__ __launch_bounds__(TPB, 7) void gll_blocked_kernel(
    const float* __restrict__ pred,
    const float* __restrict__ targ,
    const float* __restrict__ cov,
    float* __restrict__ out)
{
    const int tid = threadIdx.x;
    const int bid = blockIdx.x;
    const int b   = bid >> 2;
    const int t   = ((bid & 3) << 6) + tid;   // this thread's time index

    // cov plane (i,j) element t lives at cov[((b*16+i)*16+j)*256 + t];
    // consecutive tid -> consecutive t -> perfectly coalesced 256B runs.
    const float* covb = cov + ((size_t)b * NN * NN) * TT + t;

    // ---- Front loads: diff vector + first block-column (A11 lower + A21).
    float y[NN];
#pragma unroll
    for (int i = 0; i < NN; ++i) {
        const int off = (b * NN + i) * TT + t;
        y[i] = pred[off] - targ[off];
    }

    float A11[36];                  // rows 0..7, packed lower triangle
#pragma unroll
    for (int i = 0; i < 8; ++i)
#pragma unroll
        for (int j = 0; j <= i; ++j)
            A11[TRI(i, j)] = covb[(i * NN + j) * TT];

    float A21[8][8];                // rows 8..15 x cols 0..7
#pragma unroll
    for (int r = 0; r < 8; ++r)
#pragma unroll
        for (int j = 0; j < 8; ++j)
            A21[r][j] = covb[((8 + r) * NN + j) * TT];

    // ---- Phase 1: right-looking factorization of columns 0..7 over the full
    // 16-row panel, solve fused. Pivots >= 1 (Sigma = AA^T + I). Trailing
    // updates to columns 8..15 are deferred (that's exactly the syrk below).
    float pivprod = 1.0f;
    float quad    = 0.0f;
#pragma unroll
    for (int j = 0; j < 8; ++j) {
        const float s    = A11[TRI(j, j)];
        pivprod *= s;
        const float invd = rsqrtf(s);

        y[j] *= invd;
        quad = fmaf(y[j], y[j], quad);
#pragma unroll
        for (int i = j + 1; i < 8; ++i) A11[TRI(i, j)] *= invd;
#pragma unroll
        for (int r = 0; r < 8; ++r)     A21[r][j]      *= invd;

#pragma unroll
        for (int i = j + 1; i < 8; ++i) y[i]     = fmaf(-A11[TRI(i, j)], y[j], y[i]);
#pragma unroll
        for (int r = 0; r < 8; ++r)     y[8 + r] = fmaf(-A21[r][j],      y[j], y[8 + r]);

#pragma unroll
        for (int k = j + 1; k < 8; ++k) {
            const float ckj = A11[TRI(k, j)];
#pragma unroll
            for (int i = k; i < 8; ++i)
                A11[TRI(i, k)] = fmaf(-A11[TRI(i, j)], ckj, A11[TRI(i, k)]);
#pragma unroll
            for (int r = 0; r < 8; ++r)
                A21[r][k] = fmaf(-A21[r][j], ckj, A21[r][k]);
        }
    }

    // ---- Mid-kernel loads: A22 lower triangle (A11 registers are now dead,
    // so peak register pressure stays ~135). One MLP-36 burst; its latency
    // hides under the syrk below across 14 resident warps.
    float A22[36];                  // rows 8..15 as local 0..7, packed lower
#pragma unroll
    for (int r = 0; r < 8; ++r)
#pragma unroll
        for (int c = 0; c <= r; ++c)
            A22[TRI(r, c)] = covb[((8 + r) * NN + (8 + c)) * TT];

    // ---- syrk: A22 -= L21 * L21^T (lower triangle only)
#pragma unroll
    for (int j = 0; j < 8; ++j) {
#pragma unroll
        for (int k = 0; k < 8; ++k) {
            const float ckj = A21[k][j];
#pragma unroll
            for (int r = k; r < 8; ++r)
                A22[TRI(r, k)] = fmaf(-A21[r][j], ckj, A22[TRI(r, k)]);
        }
    }

    // ---- Phase 2: factor A22, finish the solve.
#pragma unroll
    for (int j = 0; j < 8; ++j) {
        const float s    = A22[TRI(j, j)];
        pivprod *= s;
        const float invd = rsqrtf(s);

        y[8 + j] *= invd;
        quad = fmaf(y[8 + j], y[8 + j], quad);
#pragma unroll
        for (int i = j + 1; i < 8; ++i) A22[TRI(i, j)] *= invd;

#pragma unroll
        for (int i = j + 1; i < 8; ++i)
            y[8 + i] = fmaf(-A22[TRI(i, j)], y[8 + j], y[8 + i]);

#pragma unroll
        for (int k = j + 1; k < 8; ++k) {
            const float ckj = A22[TRI(k, j)];
#pragma unroll
            for (int i = k; i < 8; ++i)
                A22[TRI(i, k)] = fmaf(-A22[TRI(i, j)], ckj, A22[TRI(i, k)]);
        }
    }

    // pivprod = det(Sigma) >= 1, comfortably within fp32 range -> one __logf.
    float v = quad + __logf(pivprod);

    // ---- In-block reduction: warp shuffles + 2-warp smem combine
    const int lane = tid & 31;
    const int wid  = tid >> 5;
#pragma unroll
    for (int o = 16; o > 0; o >>= 1) v += __shfl_down_sync(0xffffffffu, v, o);

    __shared__ float warpsum[TPB / 32];
    __shared__ bool  isLast;
    if (lane == 0) warpsum[wid] = v;
    __syncthreads();

    if (tid == 0) {
        float s = warpsum[0] + warpsum[1];
        g_partials[bid] = s;
        __threadfence();
        unsigned int c = atomicAdd(&g_count, 1u);
        isLast = (c == (unsigned int)(GRID - 1));
    }
    __syncthreads();

    // Last arriving block performs the deterministic final sum (fixed order).
    if (isLast) {
        float s = 0.0f;
#pragma unroll 8
        for (int i = tid; i < GRID; i += TPB) s += g_partials[i];
#pragma unroll
        for (int o = 16; o > 0; o >>= 1) s += __shfl_down_sync(0xffffffffu, s, o);
        if (lane == 0) warpsum[wid] = s;
        __syncthreads();
        if (tid == 0) {
            out[0] = (warpsum[0] + warpsum[1]) * (1.0f / (float)(BB * TT));
            g_count = 0;   // reset for the next graph replay
        }
    }
}

extern "C" void kernel_launch(void* const* d_in, const int* in_sizes, int n_in,
                              void* d_out, int out_size)
{
    const float* pred = (const float*)d_in[0];   // prediction [B,N,T]
    const float* targ = (const float*)d_in[1];   // target     [B,N,T]
    const float* cov  = (const float*)d_in[2];   // cov        [B,N,N,T]
    float* out = (float*)d_out;

    gll_blocked_kernel<<<GRID, TPB>>>(pred, targ, cov, out);
}